// round 7
// baseline (speedup 1.0000x reference)
#include <cuda_runtime.h>
#include <cstdint>

#define NT 60
#define ND 36
#define NL 10
#define NS 9
#define NO 8
#define KG (NL + ND)      // 46
#define MIN_ (NT*NL + NS) // 609
#define TPB 64
#define TRAJ_PER_BLK (TPB / 2)   // 32

typedef unsigned long long u64;

__device__ __forceinline__ float ex2(float x) {
    float r; asm("ex2.approx.ftz.f32 %0, %1;" : "=f"(r) : "f"(x)); return r;
}
__device__ __forceinline__ float frcp(float x) {
    float r; asm("rcp.approx.ftz.f32 %0, %1;" : "=f"(r) : "f"(x)); return r;
}
__device__ __forceinline__ void ffma2(u64& d, u64 a, u64 b) {
    asm("fma.rn.f32x2 %0, %1, %2, %0;" : "+l"(d) : "l"(a), "l"(b));
}
__device__ __forceinline__ u64 pack2(float v) {
    u64 r; asm("mov.b64 %0, {%1, %1};" : "=l"(r) : "f"(v)); return r;
}
__device__ __forceinline__ float2 unpack2(u64 v) {
    float2 f; asm("mov.b64 {%0, %1}, %2;" : "=f"(f.x), "=f"(f.y) : "l"(v)); return f;
}
// combine partial sums across a lane pair: d += shfl_xor(d, 1)
__device__ __forceinline__ void xadd2(u64& d) {
    float2 f = unpack2(d);
    float ox = __shfl_xor_sync(0xFFFFFFFFu, f.x, 1);
    float oy = __shfl_xor_sync(0xFFFFFFFFu, f.y, 1);
    u64 o; asm("mov.b64 %0, {%1, %2};" : "=l"(o) : "f"(ox), "f"(oy));
    asm("add.rn.f32x2 %0, %0, %1;" : "+l"(d) : "l"(o));
}

__device__ __forceinline__ uint32_t smem_u32(const void* p) {
    return (uint32_t)__cvta_generic_to_shared(p);
}
__device__ __forceinline__ void cpasync16(uint32_t dst, const float* src) {
    asm volatile("cp.async.cg.shared.global [%0], [%1], 16;" :: "r"(dst), "l"(src));
}
__device__ __forceinline__ void cpcommit() {
    asm volatile("cp.async.commit_group;" ::: "memory");
}
template<int N> __device__ __forceinline__ void cpwait() {
    asm volatile("cp.async.wait_group %0;" :: "n"(N) : "memory");
}

struct __align__(16) SW {
    float Wu[KG][12];     // rows padded to 48B; pre-scaled by log2e
    float Wr[KG][12];     // pre-scaled by log2e
    float Wn[KG][12];     // unscaled
    float Wo[NL][12];     // pre-scaled by 2*log2e
    float Wm[MIN_][NO];   // 32B rows
    float bu[12], br[12], bn[12], bo[12];
    float bm[NO];
    float dts[NT];
};

__global__ __launch_bounds__(TPB) void dgm2_kernel(
    const float* __restrict__ data,
    const float* __restrict__ ts,
    const float* __restrict__ stat,
    const float* __restrict__ gWu, const float* __restrict__ gbu,
    const float* __restrict__ gWr, const float* __restrict__ gbr,
    const float* __restrict__ gWn, const float* __restrict__ gbn,
    const float* __restrict__ gWo, const float* __restrict__ gbo,
    const float* __restrict__ gWm, const float* __restrict__ gbm,
    float* __restrict__ out)
{
    __shared__ SW sw;
    __shared__ __align__(16) float xs[2][TRAJ_PER_BLK * ND];
    const int tid = threadIdx.x;
    const float L2E = 1.4426950408889634f;

    // ---- stage weights (log2e pre-scaling) ----
    for (int i = tid; i < KG * NL; i += TPB) {
        int r = i / NL, c = i - r * NL;
        sw.Wu[r][c] = gWu[i] * L2E;
        sw.Wr[r][c] = gWr[i] * L2E;
        sw.Wn[r][c] = gWn[i];
    }
    for (int i = tid; i < NL * NL; i += TPB) sw.Wo[i / NL][i % NL] = gWo[i] * (2.f * L2E);
    for (int i = tid; i < MIN_ * NO; i += TPB) (&sw.Wm[0][0])[i] = gWm[i];
    if (tid < 12) { sw.bu[tid] = 0.f; sw.br[tid] = 0.f; sw.bn[tid] = 0.f; sw.bo[tid] = 0.f; }
    __syncthreads();
    if (tid < NL) {
        sw.bu[tid] = gbu[tid] * L2E;
        sw.br[tid] = gbr[tid] * L2E;
        sw.bn[tid] = gbn[tid];
        sw.bo[tid] = gbo[tid] * (2.f * L2E);
    }
    if (tid < NO) sw.bm[tid] = gbm[tid];
    for (int i = tid; i < NT; i += TPB)
        sw.dts[i] = (i == 0) ? 0.01f : (ts[i] - ts[i - 1]);
    __syncthreads();

    const int half = tid & 1;                       // which half of the reduction
    const int b = (blockIdx.x * TPB + tid) >> 1;    // trajectory
    const int tl = tid >> 1;                        // local trajectory in block

    const float* xg = data + (size_t)b * NT * ND;
    float* const xr0 = &xs[0][tl * ND];
    float* const xr1 = &xs[1][tl * ND];
    const uint32_t xs0 = smem_u32(xr0);
    const uint32_t xs1 = smem_u32(xr1);

    // per-half weight bases (loop-invariant)
    const float* wuX = &sw.Wu[NL + half * 18][0];   // x-part rows, 18 per half
    const float* wrX = &sw.Wr[NL + half * 18][0];
    const float* wnX = &sw.Wn[NL + half * 18][0];
    const float* wuY = &sw.Wu[half * 5][0];         // yo-part rows, 5 per half
    const float* wrY = &sw.Wr[half * 5][0];
    const float* wnC = &sw.Wn[half * 5][0];         // candidate rows
    const float* woH = &sw.Wo[half * 5][0];         // ODE rows

    // prefetch x[0]: lane pair splits the 9 chunks 5/4
#pragma unroll
    for (int j = 0; j < 5; j++) {
        int c = half * 5 + j;
        if (c < 9) cpasync16(xs0 + 16 * c, xg + 4 * c);
    }
    cpcommit();

    // ---- carried state: y replicated; ynp packs own half only ----
    float y[NL];
    u64 ynp[5];
    u64 acc2[4];
#pragma unroll
    for (int j = 0; j < NL; j++) y[j] = 0.f;
#pragma unroll
    for (int j = 0; j < 5; j++) ynp[j] = 0ull;
#pragma unroll
    for (int o = 0; o < 4; o++) acc2[o] = 0ull;

    const u64* bup = (const u64*)sw.bu;
    const u64* brp = (const u64*)sw.br;
    const u64* bnp = (const u64*)sw.bn;
    const u64* bop = (const u64*)sw.bo;

#pragma unroll 1
    for (int t = 0; t < NT; t++) {
        if (t + 1 < NT) {
            uint32_t dst = ((t + 1) & 1) ? xs1 : xs0;
            const float* src = xg + (t + 1) * ND;
#pragma unroll
            for (int j = 0; j < 5; j++) {
                int c = half * 5 + j;
                if (c < 9) cpasync16(dst + 16 * c, src + 4 * c);
            }
            cpcommit();
            cpwait<1>();
        } else {
            cpwait<0>();
        }
        const float* xrow = ((t & 1) ? xr1 : xr0) + half * 18;
        const float dt = sw.dts[t];
        const float dt2 = 2.f * dt;

        // ---- ODE partials over own 5 k's (bias on half0 only), combine, tanh replicated ----
        u64 og2[5];
#pragma unroll
        for (int p = 0; p < 5; p++) og2[p] = half ? 0ull : bop[p];
#pragma unroll
        for (int k = 0; k < 5; k++) {
            const float* row = woH + k * 12;
            const ulonglong2* w = (const ulonglong2*)row;
            ulonglong2 w01 = w[0], w23 = w[1];
            u64 w4 = ((const u64*)row)[4];
            ffma2(og2[0], ynp[k], w01.x);
            ffma2(og2[1], ynp[k], w01.y);
            ffma2(og2[2], ynp[k], w23.x);
            ffma2(og2[3], ynp[k], w23.y);
            ffma2(og2[4], ynp[k], w4);
        }
#pragma unroll
        for (int p = 0; p < 5; p++) xadd2(og2[p]);
        float yo[NL];
#pragma unroll
        for (int p = 0; p < 5; p++) {
            float2 g = unpack2(og2[p]);
            yo[2 * p]     = (y[2 * p] + dt)     - dt2 * frcp(ex2(g.x) + 1.f);
            yo[2 * p + 1] = (y[2 * p + 1] + dt) - dt2 * frcp(ex2(g.y) + 1.f);
        }

        // ---- GRU gate partials ----
        u64 au2[5], ar2[5], an2[5];
#pragma unroll
        for (int p = 0; p < 5; p++) {
            au2[p] = half ? 0ull : bup[p];
            ar2[p] = half ? 0ull : brp[p];
            an2[p] = half ? 0ull : bnp[p];
        }
        // x part: own 18 k's
        float xv[18];
        const float2* x2 = (const float2*)xrow;
#pragma unroll
        for (int j = 0; j < 9; j++) { float2 v = x2[j]; xv[2 * j] = v.x; xv[2 * j + 1] = v.y; }
#pragma unroll
        for (int i = 0; i < 18; i++) {
            u64 xp = pack2(xv[i]);
            const float* ru = wuX + i * 12;
            const float* rr = wrX + i * 12;
            const float* rn = wnX + i * 12;
            ulonglong2 u01 = ((const ulonglong2*)ru)[0], u23 = ((const ulonglong2*)ru)[1];
            ulonglong2 r01 = ((const ulonglong2*)rr)[0], r23 = ((const ulonglong2*)rr)[1];
            ulonglong2 n01 = ((const ulonglong2*)rn)[0], n23 = ((const ulonglong2*)rn)[1];
            u64 u4 = ((const u64*)ru)[4];
            u64 r4 = ((const u64*)rr)[4];
            u64 n4 = ((const u64*)rn)[4];
            ffma2(au2[0], xp, u01.x); ffma2(au2[1], xp, u01.y);
            ffma2(au2[2], xp, u23.x); ffma2(au2[3], xp, u23.y);
            ffma2(au2[4], xp, u4);
            ffma2(ar2[0], xp, r01.x); ffma2(ar2[1], xp, r01.y);
            ffma2(ar2[2], xp, r23.x); ffma2(ar2[3], xp, r23.y);
            ffma2(ar2[4], xp, r4);
            ffma2(an2[0], xp, n01.x); ffma2(an2[1], xp, n01.y);
            ffma2(an2[2], xp, n23.x); ffma2(an2[3], xp, n23.y);
            ffma2(an2[4], xp, n4);
        }
        // yo part for update/reset: own 5 k's
        u64 yop[5];
#pragma unroll
        for (int k = 0; k < 5; k++) yop[k] = pack2(yo[half * 5 + k]);
#pragma unroll
        for (int k = 0; k < 5; k++) {
            const float* ru = wuY + k * 12;
            const float* rr = wrY + k * 12;
            ulonglong2 u01 = ((const ulonglong2*)ru)[0], u23 = ((const ulonglong2*)ru)[1];
            ulonglong2 r01 = ((const ulonglong2*)rr)[0], r23 = ((const ulonglong2*)rr)[1];
            u64 u4 = ((const u64*)ru)[4];
            u64 r4 = ((const u64*)rr)[4];
            ffma2(au2[0], yop[k], u01.x); ffma2(au2[1], yop[k], u01.y);
            ffma2(au2[2], yop[k], u23.x); ffma2(au2[3], yop[k], u23.y);
            ffma2(au2[4], yop[k], u4);
            ffma2(ar2[0], yop[k], r01.x); ffma2(ar2[1], yop[k], r01.y);
            ffma2(ar2[2], yop[k], r23.x); ffma2(ar2[3], yop[k], r23.y);
            ffma2(ar2[4], yop[k], r4);
        }
        // combine gate partials across the pair
#pragma unroll
        for (int p = 0; p < 5; p++) { xadd2(au2[p]); xadd2(ar2[p]); xadd2(an2[p]); }

        // sigmoid (pre-scaled by log2e) — replicated on both lanes
        float u[NL], r[NL];
#pragma unroll
        for (int p = 0; p < 5; p++) {
            float2 a = unpack2(au2[p]);
            float2 rr = unpack2(ar2[p]);
            u[2 * p]     = frcp(1.f + ex2(-a.x));
            u[2 * p + 1] = frcp(1.f + ex2(-a.y));
            r[2 * p]     = frcp(1.f + ex2(-rr.x));
            r[2 * p + 1] = frcp(1.f + ex2(-rr.y));
        }
        // candidate partial: own 5 k's of (yo*r) @ Wn, then combine and add to an
        u64 anc[5];
#pragma unroll
        for (int p = 0; p < 5; p++) anc[p] = 0ull;
#pragma unroll
        for (int k = 0; k < 5; k++) {
            int kk = half * 5 + k;
            u64 cp = pack2(yo[kk] * r[kk]);
            const float* rn = wnC + k * 12;
            ulonglong2 n01 = ((const ulonglong2*)rn)[0], n23 = ((const ulonglong2*)rn)[1];
            u64 n4 = ((const u64*)rn)[4];
            ffma2(anc[0], cp, n01.x); ffma2(anc[1], cp, n01.y);
            ffma2(anc[2], cp, n23.x); ffma2(anc[3], cp, n23.y);
            ffma2(anc[4], cp, n4);
        }
#pragma unroll
        for (int p = 0; p < 5; p++) {
            xadd2(anc[p]);
            asm("add.rn.f32x2 %0, %0, %1;" : "+l"(an2[p]) : "l"(anc[p]));
        }

        float yn[NL];
#pragma unroll
        for (int p = 0; p < 5; p++) {
            float2 a = unpack2(an2[p]);
            yn[2 * p]     = a.x + u[2 * p]     * (yo[2 * p]     - a.x);
            yn[2 * p + 1] = a.y + u[2 * p + 1] * (yo[2 * p + 1] - a.y);
        }
#pragma unroll
        for (int k = 0; k < 5; k++) ynp[k] = pack2(yn[half * 5 + k]);

        // ---- fused MLP accumulation: own 5 l's (combined after loop) ----
        const float* wmrow = &sw.Wm[t * NL + half * 5][0];
#pragma unroll
        for (int l = 0; l < 5; l++) {
            const ulonglong2* wm = (const ulonglong2*)(wmrow + l * NO);
            ulonglong2 w01 = wm[0], w23 = wm[1];
            ffma2(acc2[0], ynp[l], w01.x);
            ffma2(acc2[1], ynp[l], w01.y);
            ffma2(acc2[2], ynp[l], w23.x);
            ffma2(acc2[3], ynp[l], w23.y);
        }
        // carry full y (replicated)
#pragma unroll
        for (int j = 0; j < NL; j++) y[j] = yn[j];
    }

    // ---- static part: split 5/4 across the pair ----
    const float* sp = stat + (size_t)b * NS;
#pragma unroll
    for (int j = 0; j < 5; j++) {
        int s = half * 5 + j;
        if (s < NS) {
            u64 sv = pack2(sp[s]);
            const ulonglong2* wm = (const ulonglong2*)&sw.Wm[NT * NL + s][0];
            ulonglong2 w01 = wm[0], w23 = wm[1];
            ffma2(acc2[0], sv, w01.x);
            ffma2(acc2[1], sv, w01.y);
            ffma2(acc2[2], sv, w23.x);
            ffma2(acc2[3], sv, w23.y);
        }
    }
    // combine output accumulators across the pair
#pragma unroll
    for (int o = 0; o < 4; o++) xadd2(acc2[o]);

    // each lane stores its float4 half of the 8 outputs
    float2 a0 = unpack2(acc2[half * 2]);
    float2 a1 = unpack2(acc2[half * 2 + 1]);
    float4 o0;
    o0.x = a0.x + sw.bm[half * 4 + 0];
    o0.y = a0.y + sw.bm[half * 4 + 1];
    o0.z = a1.x + sw.bm[half * 4 + 2];
    o0.w = a1.y + sw.bm[half * 4 + 3];
    *reinterpret_cast<float4*>(out + (size_t)b * NO + half * 4) = o0;
}

extern "C" void kernel_launch(void* const* d_in, const int* in_sizes, int n_in,
                              void* d_out, int out_size) {
    dgm2_kernel<<<512, TPB>>>(
        (const float*)d_in[0],   // data
        (const float*)d_in[1],   // time_steps
        (const float*)d_in[2],   // static_data
        (const float*)d_in[3],  (const float*)d_in[4],   // W_update, b_update
        (const float*)d_in[5],  (const float*)d_in[6],   // W_reset, b_reset
        (const float*)d_in[7],  (const float*)d_in[8],   // W_new, b_new
        // d_in[9], d_in[10] (W_emit, b_emit) dead — never reach the output
        (const float*)d_in[11], (const float*)d_in[12],  // W_ode, b_ode
        (const float*)d_in[13], (const float*)d_in[14],  // W_mlp, b_mlp
        (float*)d_out);
}